// round 14
// baseline (speedup 1.0000x reference)
#include <cuda_runtime.h>
#include <cuda_fp16.h>
#include <cstdint>

// ===========================================================================
// TR_Linear via fp16 HMMA GEMMs (fp32 accumulate).
//   y[b, 4q+s] = sum_k M1[q,k] * T[b, s*256+k] + bias[4q+s]
//   T = x @ Bmat            (8192x1024)(1024x1024)
// R14: 64x64 warp tiles (128B smem-read/MMA instead of 192B) — the smem
// crossbar is the measured bottleneck. 128-thread CTAs, 2 CTAs/SM.
// ===========================================================================

__device__ __half g_xh[8192 * 1024];
__device__ __half g_Th[8192 * 1024];
__device__ __half g_Bh[1024 * 1024];   // BmT[n][c]
__device__ __half g_M1[1024 * 256];    // M1[q][k]

// -------------------- helpers ----------------------------------------------
__device__ __forceinline__ uint32_t smem_u32(const void* p) {
    uint32_t a;
    asm("{ .reg .u64 t; cvta.to.shared.u64 t, %1; cvt.u32.u64 %0, t; }" : "=r"(a) : "l"(p));
    return a;
}
__device__ __forceinline__ uint32_t sw64(uint32_t off) { return off ^ ((off >> 3) & 0x30); }

__device__ __forceinline__ void cp16(uint32_t dst, const void* src) {
    asm volatile("cp.async.cg.shared.global [%0], [%1], 16;" :: "r"(dst), "l"(src));
}
__device__ __forceinline__ void cp_commit() { asm volatile("cp.async.commit_group;" ::: "memory"); }
template <int N> __device__ __forceinline__ void cp_wait() {
    asm volatile("cp.async.wait_group %0;" :: "n"(N) : "memory");
}

__device__ __forceinline__ void ldmx4(uint32_t* r, uint32_t addr) {
    asm volatile("ldmatrix.sync.aligned.m8n8.x4.shared.b16 {%0,%1,%2,%3}, [%4];"
                 : "=r"(r[0]), "=r"(r[1]), "=r"(r[2]), "=r"(r[3]) : "r"(addr));
}
__device__ __forceinline__ void mma16816(float* d, const uint32_t* a, uint32_t b0, uint32_t b1) {
    asm volatile(
        "mma.sync.aligned.m16n8k16.row.col.f32.f16.f16.f32 "
        "{%0,%1,%2,%3}, {%4,%5,%6,%7}, {%8,%9}, {%0,%1,%2,%3};"
        : "+f"(d[0]), "+f"(d[1]), "+f"(d[2]), "+f"(d[3])
        : "r"(a[0]), "r"(a[1]), "r"(a[2]), "r"(a[3]), "r"(b0), "r"(b1));
}
__device__ __forceinline__ uint32_t pack2h(float a, float b) {
    __half ha = __float2half_rn(a), hb = __float2half_rn(b);
    return (uint32_t)__half_as_ushort(ha) | ((uint32_t)__half_as_ushort(hb) << 16);
}

// -------------------- prep kernel (verified R11) ----------------------------
__global__ void prep_k(const float* __restrict__ x,
                       const float* __restrict__ c0, const float* __restrict__ c1,
                       const float* __restrict__ c2, const float* __restrict__ c3) {
    __shared__ float sc[1280];
    int b = blockIdx.x, tid = threadIdx.x;
    if (b < 4096) {
        int i = b * 256 + tid;
        const float4* xp = (const float4*)x + (size_t)i * 2;
        float4 v0 = xp[0], v1 = xp[1];
        uint4 o;
        o.x = pack2h(v0.x, v0.y); o.y = pack2h(v0.z, v0.w);
        o.z = pack2h(v1.x, v1.y); o.w = pack2h(v1.z, v1.w);
        ((uint4*)g_xh)[i] = o;
    } else if (b < 5120) {
        int n = b - 4096;
        int s = n >> 8, k = n & 255, r2 = k >> 4, r0 = k & 15;
        if (tid < 256)
            sc[tid] = __ldg(&c2[(r2 * 64 + s * 16 + (tid >> 4)) * 16 + (tid & 15)]);
        for (int t = tid; t < 1024; t += 256)
            sc[256 + t] = __ldg(&c3[((t >> 6) * 64 + (t & 63)) * 16 + r0]);
        __syncthreads();
#pragma unroll
        for (int t = 0; t < 4; ++t) {
            int c = tid + t * 256;
            int o0l = c >> 6, o1 = c & 63;
            float sum = 0.f;
#pragma unroll
            for (int r3 = 0; r3 < 16; ++r3)
                sum += sc[o0l * 16 + r3] * sc[256 + r3 * 64 + o1];
            g_Bh[(size_t)n * 1024 + c] = __float2half_rn(sum);
        }
    } else {
        int q = b - 5120;
        int q0 = q >> 5, q1 = q & 31;
        if (tid < 256) {
            sc[tid]       = __ldg(&c0[((tid >> 4) * 32 + q0) * 16 + (tid & 15)]);
            sc[256 + tid] = __ldg(&c1[((tid >> 4) * 32 + q1) * 16 + (tid & 15)]);
        }
        __syncthreads();
        int r2 = tid >> 4, r0 = tid & 15;
        float sum = 0.f;
#pragma unroll
        for (int r1 = 0; r1 < 16; ++r1)
            sum += sc[r0 * 16 + r1] * sc[256 + r1 * 16 + r2];
        g_M1[(size_t)q * 256 + tid] = __float2half_rn(sum);
    }
}

// ===========================================================================
// GEMM1: T = x @ BmT^T. CTA 128x128, BK=32, 4 warps (2x2), warp tile 64x64,
// 4-stage single-sync pipeline (prefetch distance 2), 128 threads.
// ===========================================================================
#define STAGE_BYTES 16384
#define NSTAGES 4
#define G1SMEM (1024 + NSTAGES * STAGE_BYTES)

__global__ void __launch_bounds__(128, 2) gemm1_k() {
    extern __shared__ char smem[];
    const uint32_t db = (smem_u32(smem) + 1023) & ~1023u;
    const int tid = threadIdx.x, lane = tid & 31, wid = tid >> 5;
    const int warp_m = wid & 1, warp_n = wid >> 1;     // 2 x 2
    const int rowBase = blockIdx.y * 128, colBase = blockIdx.x * 128;

    const __half* A = g_xh + (size_t)rowBase * 1024;
    const __half* B = g_Bh + (size_t)colBase * 1024;

    auto load_chunk = [&](int kc, int buf) {
        uint32_t base = db + buf * STAGE_BYTES;
#pragma unroll
        for (int it = 0; it < 4; ++it) {
            int idx = tid + it * 128;      // 0..511
            int row = idx >> 2, c16 = idx & 3;
            uint32_t so = sw64((uint32_t)(row * 64 + c16 * 16));
            cp16(base + so,        A + row * 1024 + kc * 32 + c16 * 8);
            cp16(base + 8192 + so, B + row * 1024 + kc * 32 + c16 * 8);
        }
        cp_commit();
    };

    float acc[4][8][4];
#pragma unroll
    for (int i = 0; i < 4; ++i)
#pragma unroll
        for (int j = 0; j < 8; ++j)
#pragma unroll
            for (int t = 0; t < 4; ++t) acc[i][j][t] = 0.f;

    const int rowA = warp_m * 64 + (lane & 15);
    const int a_c16half = (lane >> 4) & 1;
    const int rowB = warp_n * 64 + (lane & 7) + ((lane >> 4) << 3);
    const int b_c16half = (lane >> 3) & 1;

    load_chunk(0, 0);
    load_chunk(1, 1);

    for (int i = 0; i < 32; ++i) {
        if (i + 2 < 32) load_chunk(i + 2, (i + 2) & (NSTAGES - 1));
        if (i < 30)       cp_wait<2>();
        else if (i == 30) cp_wait<1>();
        else              cp_wait<0>();
        __syncthreads();

        uint32_t base = db + (i & (NSTAGES - 1)) * STAGE_BYTES;
#pragma unroll
        for (int ks = 0; ks < 2; ++ks) {
            uint32_t a[4][4];
#pragma unroll
            for (int mt = 0; mt < 4; ++mt) {
                uint32_t off = sw64((uint32_t)((rowA + mt * 16) * 64 + (ks * 2 + a_c16half) * 16));
                ldmx4(a[mt], base + off);
            }
            uint32_t b[8][2];
#pragma unroll
            for (int nt = 0; nt < 4; ++nt) {
                uint32_t off = sw64((uint32_t)((rowB + nt * 16) * 64 + (ks * 2 + b_c16half) * 16));
                uint32_t r[4];
                ldmx4(r, base + 8192 + off);
                b[nt * 2][0] = r[0];     b[nt * 2][1] = r[1];
                b[nt * 2 + 1][0] = r[2]; b[nt * 2 + 1][1] = r[3];
            }
#pragma unroll
            for (int mt = 0; mt < 4; ++mt)
#pragma unroll
                for (int j = 0; j < 8; ++j)
                    mma16816(acc[mt][j], a[mt], b[j][0], b[j][1]);
        }
    }

    const int r0base = rowBase + warp_m * 64 + (lane >> 2);
    const int cbase  = colBase + warp_n * 64 + (lane & 3) * 2;
#pragma unroll
    for (int mt = 0; mt < 4; ++mt)
#pragma unroll
        for (int j = 0; j < 8; ++j) {
            int r0 = r0base + mt * 16;
            int c  = cbase + j * 8;
            *(uint32_t*)(g_Th + (size_t)r0 * 1024 + c) =
                pack2h(acc[mt][j][0], acc[mt][j][1]);
            *(uint32_t*)(g_Th + (size_t)(r0 + 8) * 1024 + c) =
                pack2h(acc[mt][j][2], acc[mt][j][3]);
        }
}

// ===========================================================================
// GEMM2: out[b, 4q+s] = sum_k T[b, s*256+k] * M1[q,k] + bias
// CTA: 64 rows x 64 q x 4 s (256 contiguous out cols), 128 threads, 4 warps
// (one per s), warp tile 64r x 64q, K=256; all warps share resident B (M1).
// smem: B resident 32KB; A 3-stage x 16KB single-sync dist-1;
// epilogue: 4 phases of 16 rows x pitch-260 fp32 -> coalesced float4 stores.
// ===========================================================================
#define A2_STAGE 16384
#define EPI_PITCH 260
#define G2SMEM (1024 + 32768 + 3 * A2_STAGE)

__global__ void __launch_bounds__(128, 2) gemm2_k(float* __restrict__ Out,
                                                  const float* __restrict__ bias) {
    extern __shared__ char smem[];
    const uint32_t db = (smem_u32(smem) + 1023) & ~1023u;
    const uint32_t Bs = db;             // 32KB resident B
    const uint32_t As = db + 32768;     // 3 x 16KB A stages / epilogue buffer
    const int tid = threadIdx.x, lane = tid & 31, wid = tid >> 5;
    const int warp_s = wid;             // one warp per s
    const int rowBase = blockIdx.y * 64, qBase = blockIdx.x * 64;

    const __half* A  = g_Th + (size_t)rowBase * 1024;  // 64 rows x [s*256+k]
    const __half* Bm = g_M1 + (size_t)qBase * 256;     // 64 q x 256 k

    // --- resident B: 8 kc-subtiles of 64 rows x 64B (32KB, 2048 cp16) ---
#pragma unroll
    for (int it = 0; it < 16; ++it) {
        int idx = tid + it * 128;          // 0..2047
        int kc = idx >> 8;
        int r  = (idx >> 2) & 63;
        int c  = idx & 3;
        cp16(Bs + kc * 4096 + sw64((uint32_t)(r * 64 + c * 16)),
             Bm + r * 256 + kc * 32 + c * 8);
    }

    // --- A stage: 4 s-subtiles x 64 rows x 32 k (16KB, 1024 cp16) ---
    auto loadA = [&](int kc, int buf) {
        uint32_t base = As + buf * A2_STAGE;
#pragma unroll
        for (int it = 0; it < 8; ++it) {
            int idx = tid + it * 128;      // 0..1023
            int s   = idx >> 8;
            int row = (idx >> 2) & 63, c16 = idx & 3;
            cp16(base + s * 4096 + sw64((uint32_t)(row * 64 + c16 * 16)),
                 A + row * 1024 + s * 256 + kc * 32 + c16 * 8);
        }
        cp_commit();
    };

    loadA(0, 0);   // group 0 = B + A chunk 0

    float acc[4][8][4];
#pragma unroll
    for (int i = 0; i < 4; ++i)
#pragma unroll
        for (int j = 0; j < 8; ++j)
#pragma unroll
            for (int t = 0; t < 4; ++t) acc[i][j][t] = 0.f;

    const int rowA = lane & 15;                                   // + mt*16
    const int a_c16half = (lane >> 4) & 1;
    const int rowB = (lane & 7) + ((lane >> 4) << 3);             // + nt*16
    const int b_c16half = (lane >> 3) & 1;

    int bufi = 0;
    for (int i = 0; i < 8; ++i) {
        if (i + 1 < 8) {
            int nb = bufi + 1; if (nb == 3) nb = 0;
            loadA(i + 1, nb);
        }
        if (i < 7) cp_wait<1>(); else cp_wait<0>();
        __syncthreads();

        uint32_t abase = As + bufi * A2_STAGE + warp_s * 4096;
        uint32_t bbase = Bs + i * 4096;
#pragma unroll
        for (int ks = 0; ks < 2; ++ks) {
            uint32_t a[4][4];
#pragma unroll
            for (int mt = 0; mt < 4; ++mt) {
                uint32_t off = sw64((uint32_t)((rowA + mt * 16) * 64 + (ks * 2 + a_c16half) * 16));
                ldmx4(a[mt], abase + off);
            }
            uint32_t b[8][2];
#pragma unroll
            for (int nt = 0; nt < 4; ++nt) {
                uint32_t off = sw64((uint32_t)((rowB + nt * 16) * 64 + (ks * 2 + b_c16half) * 16));
                uint32_t r[4];
                ldmx4(r, bbase + off);
                b[nt * 2][0] = r[0];     b[nt * 2][1] = r[1];
                b[nt * 2 + 1][0] = r[2]; b[nt * 2 + 1][1] = r[3];
            }
#pragma unroll
            for (int mt = 0; mt < 4; ++mt)
#pragma unroll
                for (int j = 0; j < 8; ++j)
                    mma16816(acc[mt][j], a[mt], b[j][0], b[j][1]);
        }
        if (++bufi == 3) bufi = 0;
    }

    // --- epilogue: 4 phases of 16 rows (mt = p), pitch-260 interleave ------
    const int cbase = qBase * 4;           // 256 contiguous out cols
#pragma unroll
    for (int p = 0; p < 4; ++p) {
        __syncthreads();                   // mainloop reads (or prev phase) done
        {
            const int brow0 = (lane >> 2);             // rows brow0, brow0+8
            const int qloc0 = (lane & 3) * 2;
#pragma unroll
            for (int j = 0; j < 8; ++j) {
                int q0 = qloc0 + j * 8;
                uint32_t a0 = As + (uint32_t)(brow0       * EPI_PITCH + 4 * q0 + warp_s) * 4;
                uint32_t a1 = As + (uint32_t)(brow0       * EPI_PITCH + 4 * (q0 + 1) + warp_s) * 4;
                uint32_t a2 = As + (uint32_t)((brow0 + 8) * EPI_PITCH + 4 * q0 + warp_s) * 4;
                uint32_t a3 = As + (uint32_t)((brow0 + 8) * EPI_PITCH + 4 * (q0 + 1) + warp_s) * 4;
                asm volatile("st.shared.f32 [%0], %1;" :: "r"(a0), "f"(acc[p][j][0]));
                asm volatile("st.shared.f32 [%0], %1;" :: "r"(a1), "f"(acc[p][j][1]));
                asm volatile("st.shared.f32 [%0], %1;" :: "r"(a2), "f"(acc[p][j][2]));
                asm volatile("st.shared.f32 [%0], %1;" :: "r"(a3), "f"(acc[p][j][3]));
            }
        }
        __syncthreads();
        // coalesced float4 stores with bias: 16 rows x 64 float4s
#pragma unroll
        for (int it = 0; it < 8; ++it) {
            int idx = tid + it * 128;      // 0..1023
            int row = idx >> 6, col4 = idx & 63;
            float4 v;
            uint32_t sa = As + (uint32_t)(row * EPI_PITCH + col4 * 4) * 4;
            asm volatile("ld.shared.v4.f32 {%0,%1,%2,%3}, [%4];"
                         : "=f"(v.x), "=f"(v.y), "=f"(v.z), "=f"(v.w) : "r"(sa));
            float4 bb = __ldg((const float4*)(bias + cbase + col4 * 4));
            v.x += bb.x; v.y += bb.y; v.z += bb.z; v.w += bb.w;
            *(float4*)(Out + (size_t)(rowBase + p * 16 + row) * 4096 + cbase + col4 * 4) = v;
        }
    }
}

// ---------------------------------------------------------------------------
extern "C" void kernel_launch(void* const* d_in, const int* in_sizes, int n_in,
                              void* d_out, int out_size)
{
    const float* x    = (const float*)d_in[0];
    const float* c0   = (const float*)d_in[1];
    const float* c1   = (const float*)d_in[2];
    const float* c2   = (const float*)d_in[3];
    const float* c3   = (const float*)d_in[4];
    const float* bias = (const float*)d_in[5];
    float* out = (float*)d_out;

    cudaFuncSetAttribute(gemm1_k, cudaFuncAttributeMaxDynamicSharedMemorySize, G1SMEM);
    cudaFuncSetAttribute(gemm2_k, cudaFuncAttributeMaxDynamicSharedMemorySize, G2SMEM);

    prep_k<<<6144, 256>>>(x, c0, c1, c2, c3);

    gemm1_k<<<dim3(8, 64, 1), 128, G1SMEM>>>();
    gemm2_k<<<dim3(16, 128, 1), 128, G2SMEM>>>(out, bias);
}

// round 15
// speedup vs baseline: 1.4237x; 1.4237x over previous
#include <cuda_runtime.h>
#include <cuda_fp16.h>
#include <cstdint>

// ===========================================================================
// TR_Linear via fp16 HMMA GEMMs (fp32 accumulate).
//   y[b, 4q+s] = sum_k M1[q,k] * T[b, s*256+k] + bias[4q+s]
//   T = x @ Bmat            (8192x1024)(1024x1024)
// R15: gemm1 retried with 64x64 warp tiles, 256 thr, NO register cap
//      (R14's regression was launch_bounds(128,2) reg-cap spills).
// gemm2 / prep: verified R13 versions, untouched.
// ===========================================================================

__device__ __half g_xh[8192 * 1024];
__device__ __half g_Th[8192 * 1024];
__device__ __half g_Bh[1024 * 1024];   // BmT[n][c]
__device__ __half g_M1[1024 * 256];    // M1[q][k]

// -------------------- helpers ----------------------------------------------
__device__ __forceinline__ uint32_t smem_u32(const void* p) {
    uint32_t a;
    asm("{ .reg .u64 t; cvta.to.shared.u64 t, %1; cvt.u32.u64 %0, t; }" : "=r"(a) : "l"(p));
    return a;
}
__device__ __forceinline__ uint32_t sw64(uint32_t off) { return off ^ ((off >> 3) & 0x30); }

__device__ __forceinline__ void cp16(uint32_t dst, const void* src) {
    asm volatile("cp.async.cg.shared.global [%0], [%1], 16;" :: "r"(dst), "l"(src));
}
__device__ __forceinline__ void cp_commit() { asm volatile("cp.async.commit_group;" ::: "memory"); }
template <int N> __device__ __forceinline__ void cp_wait() {
    asm volatile("cp.async.wait_group %0;" :: "n"(N) : "memory");
}

__device__ __forceinline__ void ldmx4(uint32_t* r, uint32_t addr) {
    asm volatile("ldmatrix.sync.aligned.m8n8.x4.shared.b16 {%0,%1,%2,%3}, [%4];"
                 : "=r"(r[0]), "=r"(r[1]), "=r"(r[2]), "=r"(r[3]) : "r"(addr));
}
__device__ __forceinline__ void mma16816(float* d, const uint32_t* a, uint32_t b0, uint32_t b1) {
    asm volatile(
        "mma.sync.aligned.m16n8k16.row.col.f32.f16.f16.f32 "
        "{%0,%1,%2,%3}, {%4,%5,%6,%7}, {%8,%9}, {%0,%1,%2,%3};"
        : "+f"(d[0]), "+f"(d[1]), "+f"(d[2]), "+f"(d[3])
        : "r"(a[0]), "r"(a[1]), "r"(a[2]), "r"(a[3]), "r"(b0), "r"(b1));
}
__device__ __forceinline__ uint32_t pack2h(float a, float b) {
    __half ha = __float2half_rn(a), hb = __float2half_rn(b);
    return (uint32_t)__half_as_ushort(ha) | ((uint32_t)__half_as_ushort(hb) << 16);
}

// -------------------- prep kernel (verified R11/R13) ------------------------
__global__ void prep_k(const float* __restrict__ x,
                       const float* __restrict__ c0, const float* __restrict__ c1,
                       const float* __restrict__ c2, const float* __restrict__ c3) {
    __shared__ float sc[1280];
    int b = blockIdx.x, tid = threadIdx.x;
    if (b < 4096) {
        int i = b * 256 + tid;
        const float4* xp = (const float4*)x + (size_t)i * 2;
        float4 v0 = xp[0], v1 = xp[1];
        uint4 o;
        o.x = pack2h(v0.x, v0.y); o.y = pack2h(v0.z, v0.w);
        o.z = pack2h(v1.x, v1.y); o.w = pack2h(v1.z, v1.w);
        ((uint4*)g_xh)[i] = o;
    } else if (b < 5120) {
        int n = b - 4096;
        int s = n >> 8, k = n & 255, r2 = k >> 4, r0 = k & 15;
        if (tid < 256)
            sc[tid] = __ldg(&c2[(r2 * 64 + s * 16 + (tid >> 4)) * 16 + (tid & 15)]);
        for (int t = tid; t < 1024; t += 256)
            sc[256 + t] = __ldg(&c3[((t >> 6) * 64 + (t & 63)) * 16 + r0]);
        __syncthreads();
#pragma unroll
        for (int t = 0; t < 4; ++t) {
            int c = tid + t * 256;
            int o0l = c >> 6, o1 = c & 63;
            float sum = 0.f;
#pragma unroll
            for (int r3 = 0; r3 < 16; ++r3)
                sum += sc[o0l * 16 + r3] * sc[256 + r3 * 64 + o1];
            g_Bh[(size_t)n * 1024 + c] = __float2half_rn(sum);
        }
    } else {
        int q = b - 5120;
        int q0 = q >> 5, q1 = q & 31;
        if (tid < 256) {
            sc[tid]       = __ldg(&c0[((tid >> 4) * 32 + q0) * 16 + (tid & 15)]);
            sc[256 + tid] = __ldg(&c1[((tid >> 4) * 32 + q1) * 16 + (tid & 15)]);
        }
        __syncthreads();
        int r2 = tid >> 4, r0 = tid & 15;
        float sum = 0.f;
#pragma unroll
        for (int r1 = 0; r1 < 16; ++r1)
            sum += sc[r0 * 16 + r1] * sc[256 + r1 * 16 + r2];
        g_M1[(size_t)q * 256 + tid] = __float2half_rn(sum);
    }
}

// ===========================================================================
// GEMM1 v2: T = x @ BmT^T. CTA 128x256, BK=32, 8 warps (2m x 4n), warp tile
// 64x64, 4-stage single-sync pipeline (dist 2), 256 threads, NO reg cap.
// Stage 24KB: A (128r x 32k, 8KB) + B (256n x 32k, 16KB), SW64 rows of 64B.
// ===========================================================================
#define G1_STAGE 24576
#define NSTAGES 4
#define G1SMEM (1024 + NSTAGES * G1_STAGE)

__global__ void __launch_bounds__(256) gemm1_k() {
    extern __shared__ char smem[];
    const uint32_t db = (smem_u32(smem) + 1023) & ~1023u;
    const int tid = threadIdx.x, lane = tid & 31, wid = tid >> 5;
    const int warp_m = wid & 1, warp_n = wid >> 1;     // 2 x 4
    const int rowBase = blockIdx.y * 128, colBase = blockIdx.x * 256;

    const __half* A = g_xh + (size_t)rowBase * 1024;
    const __half* B = g_Bh + (size_t)colBase * 1024;

    auto load_chunk = [&](int kc, int buf) {
        uint32_t base = db + buf * G1_STAGE;
        // A: 128 rows x 4 c16 = 512 cp16
#pragma unroll
        for (int it = 0; it < 2; ++it) {
            int idx = tid + it * 256;
            int row = idx >> 2, c16 = idx & 3;
            uint32_t so = sw64((uint32_t)(row * 64 + c16 * 16));
            cp16(base + so, A + row * 1024 + kc * 32 + c16 * 8);
        }
        // B: 256 rows x 4 c16 = 1024 cp16
#pragma unroll
        for (int it = 0; it < 4; ++it) {
            int idx = tid + it * 256;
            int row = idx >> 2, c16 = idx & 3;
            uint32_t so = sw64((uint32_t)(row * 64 + c16 * 16));
            cp16(base + 8192 + so, B + row * 1024 + kc * 32 + c16 * 8);
        }
        cp_commit();
    };

    float acc[4][8][4];
#pragma unroll
    for (int i = 0; i < 4; ++i)
#pragma unroll
        for (int j = 0; j < 8; ++j)
#pragma unroll
            for (int t = 0; t < 4; ++t) acc[i][j][t] = 0.f;

    const int rowA = warp_m * 64 + (lane & 15);
    const int a_c16half = (lane >> 4) & 1;
    const int rowB = warp_n * 64 + (lane & 7) + ((lane >> 4) << 3);
    const int b_c16half = (lane >> 3) & 1;

    load_chunk(0, 0);
    load_chunk(1, 1);

    for (int i = 0; i < 32; ++i) {
        if (i + 2 < 32) load_chunk(i + 2, (i + 2) & (NSTAGES - 1));
        if (i < 30)       cp_wait<2>();
        else if (i == 30) cp_wait<1>();
        else              cp_wait<0>();
        __syncthreads();

        uint32_t base = db + (i & (NSTAGES - 1)) * G1_STAGE;
#pragma unroll
        for (int ks = 0; ks < 2; ++ks) {
            uint32_t a[4][4];
#pragma unroll
            for (int mt = 0; mt < 4; ++mt) {
                uint32_t off = sw64((uint32_t)((rowA + mt * 16) * 64 + (ks * 2 + a_c16half) * 16));
                ldmx4(a[mt], base + off);
            }
            uint32_t b[8][2];
#pragma unroll
            for (int nt = 0; nt < 4; ++nt) {
                uint32_t off = sw64((uint32_t)((rowB + nt * 16) * 64 + (ks * 2 + b_c16half) * 16));
                uint32_t r[4];
                ldmx4(r, base + 8192 + off);
                b[nt * 2][0] = r[0];     b[nt * 2][1] = r[1];
                b[nt * 2 + 1][0] = r[2]; b[nt * 2 + 1][1] = r[3];
            }
#pragma unroll
            for (int mt = 0; mt < 4; ++mt)
#pragma unroll
                for (int j = 0; j < 8; ++j)
                    mma16816(acc[mt][j], a[mt], b[j][0], b[j][1]);
        }
    }

    const int r0base = rowBase + warp_m * 64 + (lane >> 2);
    const int cbase  = colBase + warp_n * 64 + (lane & 3) * 2;
#pragma unroll
    for (int mt = 0; mt < 4; ++mt)
#pragma unroll
        for (int j = 0; j < 8; ++j) {
            int r0 = r0base + mt * 16;
            int c  = cbase + j * 8;
            *(uint32_t*)(g_Th + (size_t)r0 * 1024 + c) =
                pack2h(acc[mt][j][0], acc[mt][j][1]);
            *(uint32_t*)(g_Th + (size_t)(r0 + 8) * 1024 + c) =
                pack2h(acc[mt][j][2], acc[mt][j][3]);
        }
}

// ===========================================================================
// GEMM2 (verified R13): out[b, 4q+s] = sum_k T[b, s*256+k] * M1[q,k] + bias
// CTA: 64 rows x 64 q x 4 s, 256 threads, 2 CTAs/SM.
// ===========================================================================
#define A2_STAGE 16384
#define EPI_PITCH 260
#define G2SMEM (1024 + 32768 + 3 * A2_STAGE)

__global__ void __launch_bounds__(256, 2) gemm2_k(float* __restrict__ Out,
                                                  const float* __restrict__ bias) {
    extern __shared__ char smem[];
    const uint32_t db = (smem_u32(smem) + 1023) & ~1023u;
    const uint32_t Bs = db;
    const uint32_t As = db + 32768;
    const int tid = threadIdx.x, lane = tid & 31, wid = tid >> 5;
    const int warp_q = wid & 1, warp_s = wid >> 1;
    const int rowBase = blockIdx.y * 64, qBase = blockIdx.x * 64;

    const __half* A  = g_Th + (size_t)rowBase * 1024;
    const __half* Bm = g_M1 + (size_t)qBase * 256;

#pragma unroll
    for (int it = 0; it < 8; ++it) {
        int idx = tid + it * 256;
        int kc = idx >> 8;
        int r  = (idx >> 2) & 63;
        int c  = idx & 3;
        cp16(Bs + kc * 4096 + sw64((uint32_t)(r * 64 + c * 16)),
             Bm + r * 256 + kc * 32 + c * 8);
    }

    auto loadA = [&](int kc, int buf) {
        uint32_t base = As + buf * A2_STAGE;
#pragma unroll
        for (int it = 0; it < 4; ++it) {
            int idx = tid + it * 256;
            int s   = idx >> 8;
            int row = (idx >> 2) & 63, c16 = idx & 3;
            cp16(base + s * 4096 + sw64((uint32_t)(row * 64 + c16 * 16)),
                 A + row * 1024 + s * 256 + kc * 32 + c16 * 8);
        }
        cp_commit();
    };

    loadA(0, 0);

    float acc[4][4][4];
#pragma unroll
    for (int i = 0; i < 4; ++i)
#pragma unroll
        for (int j = 0; j < 4; ++j)
#pragma unroll
            for (int t = 0; t < 4; ++t) acc[i][j][t] = 0.f;

    const int rowA = lane & 15;
    const int a_c16half = (lane >> 4) & 1;
    const int rowB = warp_q * 32 + (lane & 7) + ((lane >> 4) << 3);
    const int b_c16half = (lane >> 3) & 1;

    int bufi = 0;
    for (int i = 0; i < 8; ++i) {
        if (i + 1 < 8) {
            int nb = bufi + 1; if (nb == 3) nb = 0;
            loadA(i + 1, nb);
        }
        if (i < 7) cp_wait<1>(); else cp_wait<0>();
        __syncthreads();

        uint32_t abase = As + bufi * A2_STAGE + warp_s * 4096;
        uint32_t bbase = Bs + i * 4096;
#pragma unroll
        for (int ks = 0; ks < 2; ++ks) {
            uint32_t a[4][4];
#pragma unroll
            for (int mt = 0; mt < 4; ++mt) {
                uint32_t off = sw64((uint32_t)((rowA + mt * 16) * 64 + (ks * 2 + a_c16half) * 16));
                ldmx4(a[mt], abase + off);
            }
            uint32_t b[4][2];
#pragma unroll
            for (int nt = 0; nt < 2; ++nt) {
                uint32_t off = sw64((uint32_t)((rowB + nt * 16) * 64 + (ks * 2 + b_c16half) * 16));
                uint32_t r[4];
                ldmx4(r, bbase + off);
                b[nt * 2][0] = r[0];     b[nt * 2][1] = r[1];
                b[nt * 2 + 1][0] = r[2]; b[nt * 2 + 1][1] = r[3];
            }
#pragma unroll
            for (int mt = 0; mt < 4; ++mt)
#pragma unroll
                for (int j = 0; j < 4; ++j)
                    mma16816(acc[mt][j], a[mt], b[j][0], b[j][1]);
        }
        if (++bufi == 3) bufi = 0;
    }

    const int cbase = qBase * 4;
#pragma unroll
    for (int p = 0; p < 4; ++p) {
        __syncthreads();
        {
            const int brow0 = (lane >> 2);
            const int qloc0 = warp_q * 32 + (lane & 3) * 2;
#pragma unroll
            for (int j = 0; j < 4; ++j) {
                int q0 = qloc0 + j * 8;
                uint32_t a0 = As + (uint32_t)(brow0       * EPI_PITCH + 4 * q0 + warp_s) * 4;
                uint32_t a1 = As + (uint32_t)(brow0       * EPI_PITCH + 4 * (q0 + 1) + warp_s) * 4;
                uint32_t a2 = As + (uint32_t)((brow0 + 8) * EPI_PITCH + 4 * q0 + warp_s) * 4;
                uint32_t a3 = As + (uint32_t)((brow0 + 8) * EPI_PITCH + 4 * (q0 + 1) + warp_s) * 4;
                asm volatile("st.shared.f32 [%0], %1;" :: "r"(a0), "f"(acc[p][j][0]));
                asm volatile("st.shared.f32 [%0], %1;" :: "r"(a1), "f"(acc[p][j][1]));
                asm volatile("st.shared.f32 [%0], %1;" :: "r"(a2), "f"(acc[p][j][2]));
                asm volatile("st.shared.f32 [%0], %1;" :: "r"(a3), "f"(acc[p][j][3]));
            }
        }
        __syncthreads();
#pragma unroll
        for (int it = 0; it < 4; ++it) {
            int idx = tid + it * 256;
            int row = idx >> 6, col4 = idx & 63;
            float4 v;
            uint32_t sa = As + (uint32_t)(row * EPI_PITCH + col4 * 4) * 4;
            asm volatile("ld.shared.v4.f32 {%0,%1,%2,%3}, [%4];"
                         : "=f"(v.x), "=f"(v.y), "=f"(v.z), "=f"(v.w) : "r"(sa));
            float4 bb = __ldg((const float4*)(bias + cbase + col4 * 4));
            v.x += bb.x; v.y += bb.y; v.z += bb.z; v.w += bb.w;
            *(float4*)(Out + (size_t)(rowBase + p * 16 + row) * 4096 + cbase + col4 * 4) = v;
        }
    }
}

// ---------------------------------------------------------------------------
extern "C" void kernel_launch(void* const* d_in, const int* in_sizes, int n_in,
                              void* d_out, int out_size)
{
    const float* x    = (const float*)d_in[0];
    const float* c0   = (const float*)d_in[1];
    const float* c1   = (const float*)d_in[2];
    const float* c2   = (const float*)d_in[3];
    const float* c3   = (const float*)d_in[4];
    const float* bias = (const float*)d_in[5];
    float* out = (float*)d_out;

    cudaFuncSetAttribute(gemm1_k, cudaFuncAttributeMaxDynamicSharedMemorySize, G1SMEM);
    cudaFuncSetAttribute(gemm2_k, cudaFuncAttributeMaxDynamicSharedMemorySize, G2SMEM);

    prep_k<<<6144, 256>>>(x, c0, c1, c2, c3);

    gemm1_k<<<dim3(4, 64, 1), 256, G1SMEM>>>();
    gemm2_k<<<dim3(16, 128, 1), 256, G2SMEM>>>(out, bias);
}

// round 16
// speedup vs baseline: 1.5336x; 1.0772x over previous
#include <cuda_runtime.h>
#include <cuda_fp16.h>
#include <cstdint>

// ===========================================================================
// TR_Linear via fp16 HMMA GEMMs (fp32 accumulate).
//   y[b, 4q+s] = sum_k M1[q,k] * T[b, s*256+k] + bias[4q+s]
//   T = x @ Bmat            (8192x1024)(1024x1024)
// R16: gemm1 = R13 warp shape but BK=64 (SW128 128B rows, 3-stage single-
//      sync ring) -> 16 barriers instead of 32. gemm2/prep: verified R13.
// ===========================================================================

__device__ __half g_xh[8192 * 1024];
__device__ __half g_Th[8192 * 1024];
__device__ __half g_Bh[1024 * 1024];   // BmT[n][c]
__device__ __half g_M1[1024 * 256];    // M1[q][k]

// -------------------- helpers ----------------------------------------------
__device__ __forceinline__ uint32_t smem_u32(const void* p) {
    uint32_t a;
    asm("{ .reg .u64 t; cvta.to.shared.u64 t, %1; cvt.u32.u64 %0, t; }" : "=r"(a) : "l"(p));
    return a;
}
__device__ __forceinline__ uint32_t sw64(uint32_t off)  { return off ^ ((off >> 3) & 0x30); }
__device__ __forceinline__ uint32_t sw128(uint32_t off) { return off ^ ((off >> 3) & 0x70); }

__device__ __forceinline__ void cp16(uint32_t dst, const void* src) {
    asm volatile("cp.async.cg.shared.global [%0], [%1], 16;" :: "r"(dst), "l"(src));
}
__device__ __forceinline__ void cp_commit() { asm volatile("cp.async.commit_group;" ::: "memory"); }
template <int N> __device__ __forceinline__ void cp_wait() {
    asm volatile("cp.async.wait_group %0;" :: "n"(N) : "memory");
}

__device__ __forceinline__ void ldmx4(uint32_t* r, uint32_t addr) {
    asm volatile("ldmatrix.sync.aligned.m8n8.x4.shared.b16 {%0,%1,%2,%3}, [%4];"
                 : "=r"(r[0]), "=r"(r[1]), "=r"(r[2]), "=r"(r[3]) : "r"(addr));
}
__device__ __forceinline__ void mma16816(float* d, const uint32_t* a, uint32_t b0, uint32_t b1) {
    asm volatile(
        "mma.sync.aligned.m16n8k16.row.col.f32.f16.f16.f32 "
        "{%0,%1,%2,%3}, {%4,%5,%6,%7}, {%8,%9}, {%0,%1,%2,%3};"
        : "+f"(d[0]), "+f"(d[1]), "+f"(d[2]), "+f"(d[3])
        : "r"(a[0]), "r"(a[1]), "r"(a[2]), "r"(a[3]), "r"(b0), "r"(b1));
}
__device__ __forceinline__ uint32_t pack2h(float a, float b) {
    __half ha = __float2half_rn(a), hb = __float2half_rn(b);
    return (uint32_t)__half_as_ushort(ha) | ((uint32_t)__half_as_ushort(hb) << 16);
}

// -------------------- prep kernel (verified R11/R13) ------------------------
__global__ void prep_k(const float* __restrict__ x,
                       const float* __restrict__ c0, const float* __restrict__ c1,
                       const float* __restrict__ c2, const float* __restrict__ c3) {
    __shared__ float sc[1280];
    int b = blockIdx.x, tid = threadIdx.x;
    if (b < 4096) {
        int i = b * 256 + tid;
        const float4* xp = (const float4*)x + (size_t)i * 2;
        float4 v0 = xp[0], v1 = xp[1];
        uint4 o;
        o.x = pack2h(v0.x, v0.y); o.y = pack2h(v0.z, v0.w);
        o.z = pack2h(v1.x, v1.y); o.w = pack2h(v1.z, v1.w);
        ((uint4*)g_xh)[i] = o;
    } else if (b < 5120) {
        int n = b - 4096;
        int s = n >> 8, k = n & 255, r2 = k >> 4, r0 = k & 15;
        if (tid < 256)
            sc[tid] = __ldg(&c2[(r2 * 64 + s * 16 + (tid >> 4)) * 16 + (tid & 15)]);
        for (int t = tid; t < 1024; t += 256)
            sc[256 + t] = __ldg(&c3[((t >> 6) * 64 + (t & 63)) * 16 + r0]);
        __syncthreads();
#pragma unroll
        for (int t = 0; t < 4; ++t) {
            int c = tid + t * 256;
            int o0l = c >> 6, o1 = c & 63;
            float sum = 0.f;
#pragma unroll
            for (int r3 = 0; r3 < 16; ++r3)
                sum += sc[o0l * 16 + r3] * sc[256 + r3 * 64 + o1];
            g_Bh[(size_t)n * 1024 + c] = __float2half_rn(sum);
        }
    } else {
        int q = b - 5120;
        int q0 = q >> 5, q1 = q & 31;
        if (tid < 256) {
            sc[tid]       = __ldg(&c0[((tid >> 4) * 32 + q0) * 16 + (tid & 15)]);
            sc[256 + tid] = __ldg(&c1[((tid >> 4) * 32 + q1) * 16 + (tid & 15)]);
        }
        __syncthreads();
        int r2 = tid >> 4, r0 = tid & 15;
        float sum = 0.f;
#pragma unroll
        for (int r1 = 0; r1 < 16; ++r1)
            sum += sc[r0 * 16 + r1] * sc[256 + r1 * 16 + r2];
        g_M1[(size_t)q * 256 + tid] = __float2half_rn(sum);
    }
}

// ===========================================================================
// GEMM1: T = x @ BmT^T. CTA 128x128, BK=64 (SW128, 128B rows), 8 warps
// (2m x 4n), warp tile 64x32, 3-stage 32KB single-sync ring (dist 1).
// 16 chunks -> 16 barriers (was 32).
// ===========================================================================
#define G1_STAGE 32768
#define G1SMEM (1024 + 3 * G1_STAGE)

__global__ void __launch_bounds__(256, 2) gemm1_k() {
    extern __shared__ char smem[];
    const uint32_t db = (smem_u32(smem) + 1023) & ~1023u;
    const int tid = threadIdx.x, lane = tid & 31, wid = tid >> 5;
    const int warp_m = wid & 1, warp_n = wid >> 1;
    const int rowBase = blockIdx.y * 128, colBase = blockIdx.x * 128;

    const __half* A = g_xh + (size_t)rowBase * 1024;
    const __half* B = g_Bh + (size_t)colBase * 1024;

    // stage: A 128 rows x 128B (16KB) + B 128 rows x 128B (16KB)
    auto load_chunk = [&](int kc, int buf) {
        uint32_t base = db + buf * G1_STAGE;
#pragma unroll
        for (int it = 0; it < 4; ++it) {
            int idx = tid + it * 256;          // 0..1023
            int row = idx >> 3, c16 = idx & 7; // 128 rows x 8 c16
            uint32_t so = sw128((uint32_t)(row * 128 + c16 * 16));
            cp16(base + so,         A + row * 1024 + kc * 64 + c16 * 8);
            cp16(base + 16384 + so, B + row * 1024 + kc * 64 + c16 * 8);
        }
        cp_commit();
    };

    float acc[4][4][4];
#pragma unroll
    for (int i = 0; i < 4; ++i)
#pragma unroll
        for (int j = 0; j < 4; ++j)
#pragma unroll
            for (int t = 0; t < 4; ++t) acc[i][j][t] = 0.f;

    const int rowA = warp_m * 64 + (lane & 15);
    const int a_c16half = (lane >> 4) & 1;
    const int rowB = warp_n * 32 + (lane & 7) + ((lane >> 4) << 3);
    const int b_c16half = (lane >> 3) & 1;

    load_chunk(0, 0);

    int bufi = 0;
    for (int i = 0; i < 16; ++i) {
        if (i + 1 < 16) {
            int nb = bufi + 1; if (nb == 3) nb = 0;
            load_chunk(i + 1, nb);
        }
        if (i < 15) cp_wait<1>(); else cp_wait<0>();
        __syncthreads();

        uint32_t base = db + bufi * G1_STAGE;
#pragma unroll
        for (int ks = 0; ks < 4; ++ks) {
            uint32_t a[4][4];
#pragma unroll
            for (int mt = 0; mt < 4; ++mt) {
                uint32_t off = sw128((uint32_t)((rowA + mt * 16) * 128 + (ks * 2 + a_c16half) * 16));
                ldmx4(a[mt], base + off);
            }
            uint32_t b[4][2];
#pragma unroll
            for (int nt = 0; nt < 2; ++nt) {
                uint32_t off = sw128((uint32_t)((rowB + nt * 16) * 128 + (ks * 2 + b_c16half) * 16));
                uint32_t r[4];
                ldmx4(r, base + 16384 + off);
                b[nt * 2][0] = r[0];     b[nt * 2][1] = r[1];
                b[nt * 2 + 1][0] = r[2]; b[nt * 2 + 1][1] = r[3];
            }
#pragma unroll
            for (int mt = 0; mt < 4; ++mt)
#pragma unroll
                for (int j = 0; j < 4; ++j)
                    mma16816(acc[mt][j], a[mt], b[j][0], b[j][1]);
        }
        if (++bufi == 3) bufi = 0;
    }

    const int r0base = rowBase + warp_m * 64 + (lane >> 2);
    const int cbase  = colBase + warp_n * 32 + (lane & 3) * 2;
#pragma unroll
    for (int mt = 0; mt < 4; ++mt)
#pragma unroll
        for (int j = 0; j < 4; ++j) {
            int r0 = r0base + mt * 16;
            int c  = cbase + j * 8;
            *(uint32_t*)(g_Th + (size_t)r0 * 1024 + c) =
                pack2h(acc[mt][j][0], acc[mt][j][1]);
            *(uint32_t*)(g_Th + (size_t)(r0 + 8) * 1024 + c) =
                pack2h(acc[mt][j][2], acc[mt][j][3]);
        }
}

// ===========================================================================
// GEMM2 (verified R13): out[b, 4q+s] = sum_k T[b, s*256+k] * M1[q,k] + bias
// CTA: 64 rows x 64 q x 4 s, 256 threads, 2 CTAs/SM.
// ===========================================================================
#define A2_STAGE 16384
#define EPI_PITCH 260
#define G2SMEM (1024 + 32768 + 3 * A2_STAGE)

__global__ void __launch_bounds__(256, 2) gemm2_k(float* __restrict__ Out,
                                                  const float* __restrict__ bias) {
    extern __shared__ char smem[];
    const uint32_t db = (smem_u32(smem) + 1023) & ~1023u;
    const uint32_t Bs = db;
    const uint32_t As = db + 32768;
    const int tid = threadIdx.x, lane = tid & 31, wid = tid >> 5;
    const int warp_q = wid & 1, warp_s = wid >> 1;
    const int rowBase = blockIdx.y * 64, qBase = blockIdx.x * 64;

    const __half* A  = g_Th + (size_t)rowBase * 1024;
    const __half* Bm = g_M1 + (size_t)qBase * 256;

#pragma unroll
    for (int it = 0; it < 8; ++it) {
        int idx = tid + it * 256;
        int kc = idx >> 8;
        int r  = (idx >> 2) & 63;
        int c  = idx & 3;
        cp16(Bs + kc * 4096 + sw64((uint32_t)(r * 64 + c * 16)),
             Bm + r * 256 + kc * 32 + c * 8);
    }

    auto loadA = [&](int kc, int buf) {
        uint32_t base = As + buf * A2_STAGE;
#pragma unroll
        for (int it = 0; it < 4; ++it) {
            int idx = tid + it * 256;
            int s   = idx >> 8;
            int row = (idx >> 2) & 63, c16 = idx & 3;
            cp16(base + s * 4096 + sw64((uint32_t)(row * 64 + c16 * 16)),
                 A + row * 1024 + s * 256 + kc * 32 + c16 * 8);
        }
        cp_commit();
    };

    loadA(0, 0);

    float acc[4][4][4];
#pragma unroll
    for (int i = 0; i < 4; ++i)
#pragma unroll
        for (int j = 0; j < 4; ++j)
#pragma unroll
            for (int t = 0; t < 4; ++t) acc[i][j][t] = 0.f;

    const int rowA = lane & 15;
    const int a_c16half = (lane >> 4) & 1;
    const int rowB = warp_q * 32 + (lane & 7) + ((lane >> 4) << 3);
    const int b_c16half = (lane >> 3) & 1;

    int bufi = 0;
    for (int i = 0; i < 8; ++i) {
        if (i + 1 < 8) {
            int nb = bufi + 1; if (nb == 3) nb = 0;
            loadA(i + 1, nb);
        }
        if (i < 7) cp_wait<1>(); else cp_wait<0>();
        __syncthreads();

        uint32_t abase = As + bufi * A2_STAGE + warp_s * 4096;
        uint32_t bbase = Bs + i * 4096;
#pragma unroll
        for (int ks = 0; ks < 2; ++ks) {
            uint32_t a[4][4];
#pragma unroll
            for (int mt = 0; mt < 4; ++mt) {
                uint32_t off = sw64((uint32_t)((rowA + mt * 16) * 64 + (ks * 2 + a_c16half) * 16));
                ldmx4(a[mt], abase + off);
            }
            uint32_t b[4][2];
#pragma unroll
            for (int nt = 0; nt < 2; ++nt) {
                uint32_t off = sw64((uint32_t)((rowB + nt * 16) * 64 + (ks * 2 + b_c16half) * 16));
                uint32_t r[4];
                ldmx4(r, bbase + off);
                b[nt * 2][0] = r[0];     b[nt * 2][1] = r[1];
                b[nt * 2 + 1][0] = r[2]; b[nt * 2 + 1][1] = r[3];
            }
#pragma unroll
            for (int mt = 0; mt < 4; ++mt)
#pragma unroll
                for (int j = 0; j < 4; ++j)
                    mma16816(acc[mt][j], a[mt], b[j][0], b[j][1]);
        }
        if (++bufi == 3) bufi = 0;
    }

    const int cbase = qBase * 4;
#pragma unroll
    for (int p = 0; p < 4; ++p) {
        __syncthreads();
        {
            const int brow0 = (lane >> 2);
            const int qloc0 = warp_q * 32 + (lane & 3) * 2;
#pragma unroll
            for (int j = 0; j < 4; ++j) {
                int q0 = qloc0 + j * 8;
                uint32_t a0 = As + (uint32_t)(brow0       * EPI_PITCH + 4 * q0 + warp_s) * 4;
                uint32_t a1 = As + (uint32_t)(brow0       * EPI_PITCH + 4 * (q0 + 1) + warp_s) * 4;
                uint32_t a2 = As + (uint32_t)((brow0 + 8) * EPI_PITCH + 4 * q0 + warp_s) * 4;
                uint32_t a3 = As + (uint32_t)((brow0 + 8) * EPI_PITCH + 4 * (q0 + 1) + warp_s) * 4;
                asm volatile("st.shared.f32 [%0], %1;" :: "r"(a0), "f"(acc[p][j][0]));
                asm volatile("st.shared.f32 [%0], %1;" :: "r"(a1), "f"(acc[p][j][1]));
                asm volatile("st.shared.f32 [%0], %1;" :: "r"(a2), "f"(acc[p][j][2]));
                asm volatile("st.shared.f32 [%0], %1;" :: "r"(a3), "f"(acc[p][j][3]));
            }
        }
        __syncthreads();
#pragma unroll
        for (int it = 0; it < 4; ++it) {
            int idx = tid + it * 256;
            int row = idx >> 6, col4 = idx & 63;
            float4 v;
            uint32_t sa = As + (uint32_t)(row * EPI_PITCH + col4 * 4) * 4;
            asm volatile("ld.shared.v4.f32 {%0,%1,%2,%3}, [%4];"
                         : "=f"(v.x), "=f"(v.y), "=f"(v.z), "=f"(v.w) : "r"(sa));
            float4 bb = __ldg((const float4*)(bias + cbase + col4 * 4));
            v.x += bb.x; v.y += bb.y; v.z += bb.z; v.w += bb.w;
            *(float4*)(Out + (size_t)(rowBase + p * 16 + row) * 4096 + cbase + col4 * 4) = v;
        }
    }
}

// ---------------------------------------------------------------------------
extern "C" void kernel_launch(void* const* d_in, const int* in_sizes, int n_in,
                              void* d_out, int out_size)
{
    const float* x    = (const float*)d_in[0];
    const float* c0   = (const float*)d_in[1];
    const float* c1   = (const float*)d_in[2];
    const float* c2   = (const float*)d_in[3];
    const float* c3   = (const float*)d_in[4];
    const float* bias = (const float*)d_in[5];
    float* out = (float*)d_out;

    cudaFuncSetAttribute(gemm1_k, cudaFuncAttributeMaxDynamicSharedMemorySize, G1SMEM);
    cudaFuncSetAttribute(gemm2_k, cudaFuncAttributeMaxDynamicSharedMemorySize, G2SMEM);

    prep_k<<<6144, 256>>>(x, c0, c1, c2, c3);

    gemm1_k<<<dim3(8, 64, 1), 256, G1SMEM>>>();
    gemm2_k<<<dim3(16, 128, 1), 256, G2SMEM>>>(out, bias);
}